// round 13
// baseline (speedup 1.0000x reference)
#include <cuda_runtime.h>
#include <cuda_bf16.h>
#include <math.h>

#define NIMG   4
#define NPROP  2000
#define MAXGT  64
#define HH     512
#define WW     512
#define PPOS   66
#define NNEG   134
#define NROIS  200
#define MH     28
#define MW     28
#define EPSF   1e-8f
#define NWORDS (NPROP / 4)        // 500 packed flag words per image
#define NIOU_BLOCKS (NPROP / 8 * NIMG)          // 1000 blocks in k_iou grid
#define NQ8    (NIMG * NROIS * (MH * MW / 8))   // 78400 8-pixel units

// Output layout (float32, concatenated flattened tuple):
//   rois    [4][200][4]     @ 0      (3200)
//   class   [4][200]        @ 3200   (800)
//   deltas  [4][200][4]     @ 4000   (3200)
//   masks   [4][200][28][28]@ 7200   (627200)
#define OFF_ROIS  0
#define OFF_CLS   3200
#define OFF_DEL   4000
#define OFF_MSK   7200

// XLA rewrites x / const into x * (1/const) (algebraic simplifier).
#define RCP_033  (1.0f / 0.33f)   // 66*r rounds to exactly 200.0f
#define RCP_01   (1.0f / 0.1f)    // exactly 10.0f
#define RCP_02   (1.0f / 0.2f)    // exactly 5.0f
#define RCP_27   (1.0f / 27.0f)

// ---------------- device scratch (no allocations allowed) ----------------
__device__ int            g_best[NIMG][NPROP];
__device__ unsigned char  g_posf[NIMG][NPROP];   // 0/1 bytes
__device__ unsigned char  g_negf[NIMG][NPROP];
__device__ int            g_pos_idx[NIMG][PPOS];
__device__ int            g_pos_count[NIMG];
__device__ int            g_mask_fmt;            // 0=u8, 1=i32, 2=f32, 3=bf16
__device__ int            g_done = 0;            // fence+atomic tail counter

__device__ __forceinline__ float mask_at(const void* m, int fmt, int idx) {
    switch (fmt) {
        case 0:  return (float)__ldg((const unsigned char*)m + idx);
        case 1:  return (float)__ldg((const int*)m + idx);
        case 3: {
            unsigned short u = __ldg((const unsigned short*)m + idx);
            __nv_bfloat16 v;
            *(unsigned short*)&v = u;
            return __bfloat162float(v);
        }
        default: return __ldg((const float*)m + idx);
    }
}

// ---- stable first-k chunk compaction (warp-collective) ----
__device__ __forceinline__ int chunk_scan(const unsigned* __restrict__ w,
                                          int lane, int cap, int* s_out) {
    const int base = lane * 16;
    int c = 0;
    #pragma unroll
    for (int t = 0; t < 16; ++t) {
        const int wi = base + t;
        if (wi < NWORDS) c += __popc(__ldg(w + wi));
    }
    int inc = c;
    #pragma unroll
    for (int off = 1; off < 32; off <<= 1) {
        int up = __shfl_up_sync(0xFFFFFFFFu, inc, off);
        if (lane >= off) inc += up;
    }
    const int tot = __shfl_sync(0xFFFFFFFFu, inc, 31);
    int r = inc - c;
    if (c > 0 && r < cap) {
        for (int t = 0; t < 16; ++t) {
            const int wi = base + t;
            unsigned x = (wi < NWORDS) ? __ldg(w + wi) : 0u;
            if (!x) continue;
            #pragma unroll
            for (int b = 0; b < 4; ++b)
                if ((x >> (8 * b)) & 1u) {
                    if (r < cap) s_out[r] = wi * 4 + b;
                    r++;
                }
        }
    }
    return tot;
}

// ---------------- IoU / flags + tail-block select/emit ----------------
// One warp per proposal (8/block, grid (250,4)). After flag writes each
// block fences + atomics g_done; the LAST block runs select+emit for all 4
// images (deterministic: the work is identical whichever block is last).
__global__ void __launch_bounds__(256)
k_iou(const float* __restrict__ props,
      const int*   __restrict__ ids,
      const float* __restrict__ gtb,
      const uint4* __restrict__ masks_raw,
      float* __restrict__ out) {
    const int img  = blockIdx.y;
    const int wid  = threadIdx.x >> 5;
    const int lane = threadIdx.x & 31;
    const int prop = blockIdx.x * 8 + wid;   // 250*8 = 2000

    __shared__ float4 sgt[MAXGT];
    __shared__ int    sfl[MAXGT];   // bit0: gt_valid, bit1: crowd
    if (threadIdx.x < MAXGT) {
        const float* g = gtb + (img * MAXGT + threadIdx.x) * 4;
        float4 b; b.x = g[0]; b.y = g[1]; b.z = g[2]; b.w = g[3];
        sgt[threadIdx.x] = b;
        int id = ids[img * MAXGT + threadIdx.x];
        bool bv = (b.x != 0.f) || (b.y != 0.f) || (b.z != 0.f) || (b.w != 0.f);
        sfl[threadIdx.x] = ((bv && id > 0) ? 1 : 0) | ((bv && id < 0) ? 2 : 0);
    }
    __syncthreads();

    const float4 p = *(const float4*)(props + (img * NPROP + prop) * 4);
    const float py1 = p.x, px1 = p.y, py2 = p.z, px2 = p.w;
    const bool prop_valid = (py1 != 0.f) || (px1 != 0.f) || (py2 != 0.f) || (px2 != 0.f);
    const float a1 = __fmul_rn(__fsub_rn(py2, py1), __fsub_rn(px2, px1));

    float best = -INFINITY; int bi = 0;
    float crowd_max = -1.0f;
    #pragma unroll
    for (int t = 0; t < 2; ++t) {
        const int j = lane + 32 * t;
        float4 g = sgt[j];
        int fl = sfl[j];
        float ih = fmaxf(__fsub_rn(fminf(py2, g.z), fmaxf(py1, g.x)), 0.0f);
        float iw = fmaxf(__fsub_rn(fminf(px2, g.w), fmaxf(px1, g.y)), 0.0f);
        float inter = __fmul_rn(ih, iw);
        float a2 = __fmul_rn(__fsub_rn(g.z, g.x), __fsub_rn(g.w, g.y));
        float denom = __fadd_rn(__fsub_rn(__fadd_rn(a1, a2), inter), EPSF);
        float iou = __fdiv_rn(inter, denom);
        float ov = (fl & 1) ? iou : -1.0f;
        if (ov > best) { best = ov; bi = j; }   // j < j+32: first-max kept
        float cv = (fl & 2) ? iou : -1.0f;
        crowd_max = fmaxf(crowd_max, cv);
    }

    #pragma unroll
    for (int off = 16; off > 0; off >>= 1) {
        float ob = __shfl_xor_sync(0xFFFFFFFFu, best, off);
        int   oi = __shfl_xor_sync(0xFFFFFFFFu, bi, off);
        float oc = __shfl_xor_sync(0xFFFFFFFFu, crowd_max, off);
        if (ob > best || (ob == best && oi < bi)) { best = ob; bi = oi; }
        crowd_max = fmaxf(crowd_max, oc);
    }

    if (lane == 0) {
        bool pos = (best >= 0.5f) && prop_valid;
        bool neg = (best < 0.5f) && (crowd_max < 0.001f) && prop_valid && !pos;
        g_best[img][prop] = bi;
        g_posf[img][prop] = pos ? 1 : 0;
        g_negf[img][prop] = neg ? 1 : 0;
    }

    // ---- one-time mask dtype probe (block (0,0), warp 0) ----
    if (blockIdx.x == 0 && img == 0 && wid == 0) {
        int a = 0, b = 0, c = 0;
        #pragma unroll
        for (int t = 0; t < 8; ++t) {           // 8*32 uint4 = 4096 bytes
            uint4 v = __ldg(masks_raw + t * 32 + lane);
            unsigned ws[4] = {v.x, v.y, v.z, v.w};
            #pragma unroll
            for (int q = 0; q < 4; ++q) {
                unsigned w = ws[q];
                unsigned b0 = w & 0xFFu, b1 = (w >> 8) & 0xFFu;
                unsigned b2 = (w >> 16) & 0xFFu, b3 = (w >> 24) & 0xFFu;
                if (b0 > 1u || b1 > 1u || b2 > 1u || b3 > 1u) a = 1;
                if (b1 != 0u) b = 1;
                if (b1 == 1u || b2 == 1u || b3 == 1u) c = 1;
            }
        }
        unsigned am = __ballot_sync(0xFFFFFFFFu, a);
        unsigned bm = __ballot_sync(0xFFFFFFFFu, b);
        unsigned cm = __ballot_sync(0xFFFFFFFFu, c);
        if (lane == 0) {
            int fmt;
            if (am) fmt = bm ? 3 : 2;
            else    fmt = cm ? 0 : 1;
            g_mask_fmt = fmt;
        }
    }

    // ---- fence + atomic tail: last block runs select + emit ----
    __shared__ int s_last;
    __syncthreads();
    if (threadIdx.x == 0) {
        __threadfence();                          // publish flags/best
        int old = atomicAdd(&g_done, 1);
        s_last = (old == NIOU_BLOCKS - 1) ? 1 : 0;
        if (s_last) g_done = 0;                   // self-reset for next replay
    }
    __syncthreads();
    if (!s_last) return;
    __threadfence();                              // acquire all blocks' flags

    __shared__ int s_pos_idx[NIMG][PPOS];
    __shared__ int s_neg_idx[NIMG][NNEG];
    __shared__ int s_ptot[NIMG], s_ntot[NIMG];

    // 8 warps: warp w scans image w/2, pos if w even else neg.
    {
        const int im = wid >> 1;
        if (im < NIMG) {
            if ((wid & 1) == 0) {
                int pt = chunk_scan((const unsigned*)&g_posf[im][0], lane,
                                    PPOS, s_pos_idx[im]);
                if (lane == 0) s_ptot[im] = pt;
            } else {
                int nt = chunk_scan((const unsigned*)&g_negf[im][0], lane,
                                    NNEG, s_neg_idx[im]);
                if (lane == 0) s_ntot[im] = nt;
            }
        }
    }
    __syncthreads();

    for (int im = 0; im < NIMG; ++im) {
        const int pos_count = s_ptot[im] < PPOS ? s_ptot[im] : PPOS;
        if (threadIdx.x < PPOS) g_pos_idx[im][threadIdx.x] = s_pos_idx[im][threadIdx.x];
        if (threadIdx.x == 0)   g_pos_count[im] = pos_count;

        const int k = threadIdx.x;
        if (k < NROIS) {
            float r0 = 0.f, r1 = 0.f, r2 = 0.f, r3 = 0.f;
            float cls = 0.f;
            float d0 = 0.f, d1 = 0.f, d2 = 0.f, d3 = 0.f;
            if (k < PPOS) {
                if (k < pos_count) {
                    int idx = s_pos_idx[im][k];
                    const float* pp = props + (im * NPROP + idx) * 4;
                    r0 = pp[0]; r1 = pp[1]; r2 = pp[2]; r3 = pp[3];
                    int bg = g_best[im][idx];
                    cls = (float)ids[im * MAXGT + bg];
                    const float* g = gtb + (im * MAXGT + bg) * 4;
                    float gy1 = g[0], gx1 = g[1], gy2 = g[2], gx2 = g[3];
                    float h  = fmaxf(__fsub_rn(r2, r0), EPSF);
                    float w  = fmaxf(__fsub_rn(r3, r1), EPSF);
                    float cy = __fadd_rn(r0, __fmul_rn(0.5f, h));
                    float cx = __fadd_rn(r1, __fmul_rn(0.5f, w));
                    float gh = fmaxf(__fsub_rn(gy2, gy1), EPSF);
                    float gw = fmaxf(__fsub_rn(gx2, gx1), EPSF);
                    float gcy = __fadd_rn(gy1, __fmul_rn(0.5f, gh));
                    float gcx = __fadd_rn(gx1, __fmul_rn(0.5f, gw));
                    d0 = __fmul_rn(__fdiv_rn(__fsub_rn(gcy, cy), h), RCP_01);
                    d1 = __fmul_rn(__fdiv_rn(__fsub_rn(gcx, cx), w), RCP_01);
                    d2 = __fmul_rn(logf(__fdiv_rn(gh, h)), RCP_02);
                    d3 = __fmul_rn(logf(__fdiv_rn(gw, w)), RCP_02);
                }
            } else {
                int neg_target = (int)(__fmul_rn((float)pos_count, RCP_033)) - pos_count;
                int avail = s_ntot[im] < NNEG ? s_ntot[im] : NNEG;
                int neg_count = neg_target < 0 ? 0 : (neg_target < avail ? neg_target : avail);
                int j = k - PPOS;
                if (j < neg_count) {
                    int idx = s_neg_idx[im][j];
                    const float* pp = props + (im * NPROP + idx) * 4;
                    r0 = pp[0]; r1 = pp[1]; r2 = pp[2]; r3 = pp[3];
                }
            }
            int row = im * NROIS + k;
            float* rois = out + OFF_ROIS + row * 4;
            rois[0] = r0; rois[1] = r1; rois[2] = r2; rois[3] = r3;
            out[OFF_CLS + row] = cls;
            float* del = out + OFF_DEL + row * 4;
            del[0] = d0; del[1] = d1; del[2] = d2; del[3] = d3;
        }
    }
}

// ---------------- mask crop-resize: 8 pixels (2 float4) per thread ----------------
// 32 independent gathers in flight per warp slot; metadata loaded once.
__global__ void __launch_bounds__(256)
k_masks(const float* __restrict__ props,
        const void*  __restrict__ masks,
        float* __restrict__ out) {
    const int q = blockIdx.x * 256 + threadIdx.x;
    if (q >= NQ8) return;
    const int img = q / (NROIS * 98);
    const int rem = q % (NROIS * 98);
    const int k   = rem / 98;
    const int t8  = (rem % 98) * 8;

    float v[8];
    #pragma unroll
    for (int u = 0; u < 8; ++u) v[u] = 0.0f;

    if (k < __ldg(&g_pos_count[img])) {      // only pos rows have masks
        const int fmt = g_mask_fmt;
        const int idx = __ldg(&g_pos_idx[img][k]);
        const int g   = __ldg(&g_best[img][idx]);
        const float4 pb = __ldg((const float4*)(props + (img * NPROP + idx) * 4));
        const float y1 = pb.x, x1 = pb.y, y2 = pb.z, x2 = pb.w;
        #pragma unroll
        for (int u = 0; u < 8; ++u) {
            const int t = t8 + u;
            const int i = t / MW, j = t % MW;
            float iy = __fmul_rn((float)i, RCP_27);
            float ix = __fmul_rn((float)j, RCP_27);
            float ys = __fmul_rn(__fadd_rn(y1, __fmul_rn(iy, __fsub_rn(y2, y1))), (float)(HH - 1));
            float xs = __fmul_rn(__fadd_rn(x1, __fmul_rn(ix, __fsub_rn(x2, x1))), (float)(WW - 1));
            float y0f = floorf(ys), x0f = floorf(xs);
            float ly = __fsub_rn(ys, y0f);
            float lx = __fsub_rn(xs, x0f);
            int y0  = min(max((int)y0f, 0), HH - 1);
            int y1i = min(y0 + 1, HH - 1);
            int x0  = min(max((int)x0f, 0), WW - 1);
            int x1i = min(x0 + 1, WW - 1);
            int rowbase0 = (img * HH + y0)  * WW;
            int rowbase1 = (img * HH + y1i) * WW;
            float v00 = mask_at(masks, fmt, (rowbase0 + x0)  * MAXGT + g);
            float v01 = mask_at(masks, fmt, (rowbase0 + x1i) * MAXGT + g);
            float v10 = mask_at(masks, fmt, (rowbase1 + x0)  * MAXGT + g);
            float v11 = mask_at(masks, fmt, (rowbase1 + x1i) * MAXGT + g);
            float omlx = __fsub_rn(1.0f, lx);
            float omly = __fsub_rn(1.0f, ly);
            float top = __fadd_rn(__fmul_rn(v00, omlx), __fmul_rn(v01, lx));
            float bot = __fadd_rn(__fmul_rn(v10, omlx), __fmul_rn(v11, lx));
            v[u] = rintf(__fadd_rn(__fmul_rn(top, omly), __fmul_rn(bot, ly)));  // half-to-even
        }
    }
    float* dst = out + OFF_MSK + (img * NROIS + k) * (MH * MW) + t8;
    *(float4*)(dst)     = make_float4(v[0], v[1], v[2], v[3]);
    *(float4*)(dst + 4) = make_float4(v[4], v[5], v[6], v[7]);
}

// ---------------- launch ----------------
extern "C" void kernel_launch(void* const* d_in, const int* in_sizes, int n_in,
                              void* d_out, int out_size) {
    const float* props = (const float*)d_in[0];
    const int*   ids   = (const int*)  d_in[1];
    const float* gtb   = (const float*)d_in[2];
    const void*  masks = d_in[3];
    float* out = (float*)d_out;

    k_iou<<<dim3(NPROP / 8, NIMG), 256>>>(props, ids, gtb, (const uint4*)masks, out);
    k_masks<<<(NQ8 + 255) / 256, 256>>>(props, masks, out);
}

// round 14
// speedup vs baseline: 1.1632x; 1.1632x over previous
#include <cuda_runtime.h>
#include <cuda_bf16.h>
#include <math.h>

#define NIMG   4
#define NPROP  2000
#define MAXGT  64
#define HH     512
#define WW     512
#define PPOS   66
#define NNEG   134
#define NROIS  200
#define MH     28
#define MW     28
#define EPSF   1e-8f
#define NWORDS (NPROP / 4)        // 500 packed flag words per image
#define NIOU_BLOCKS (NPROP / 8 * NIMG)          // 1000 blocks in k_iou grid
#define NQ2    (NIMG * NROIS * (MH * MW / 2))   // 313600 2-pixel units

// Output layout (float32, concatenated flattened tuple):
//   rois    [4][200][4]     @ 0      (3200)
//   class   [4][200]        @ 3200   (800)
//   deltas  [4][200][4]     @ 4000   (3200)
//   masks   [4][200][28][28]@ 7200   (627200)
#define OFF_ROIS  0
#define OFF_CLS   3200
#define OFF_DEL   4000
#define OFF_MSK   7200

// XLA rewrites x / const into x * (1/const) (algebraic simplifier).
#define RCP_033  (1.0f / 0.33f)   // 66*r rounds to exactly 200.0f
#define RCP_01   (1.0f / 0.1f)    // exactly 10.0f
#define RCP_02   (1.0f / 0.2f)    // exactly 5.0f
#define RCP_27   (1.0f / 27.0f)

// ---------------- device scratch (no allocations allowed) ----------------
__device__ int            g_best[NIMG][NPROP];
__device__ unsigned char  g_posf[NIMG][NPROP];   // 0/1 bytes
__device__ unsigned char  g_negf[NIMG][NPROP];
__device__ int            g_mgt[NIMG][PPOS];     // gt index per pos row, -1 = zero row
__device__ float4         g_mbox[NIMG][PPOS];    // roi box per pos row
__device__ int            g_mask_fmt;            // 0=u8, 1=i32, 2=f32, 3=bf16
__device__ int            g_done = 0;            // fence+atomic tail counter

__device__ __forceinline__ float mask_at(const void* m, int fmt, int idx) {
    switch (fmt) {
        case 0:  return (float)__ldg((const unsigned char*)m + idx);
        case 1:  return (float)__ldg((const int*)m + idx);
        case 3: {
            unsigned short u = __ldg((const unsigned short*)m + idx);
            __nv_bfloat16 v;
            *(unsigned short*)&v = u;
            return __bfloat162float(v);
        }
        default: return __ldg((const float*)m + idx);
    }
}

// ---- stable first-k chunk compaction (warp-collective) ----
__device__ __forceinline__ int chunk_scan(const unsigned* __restrict__ w,
                                          int lane, int cap, int* s_out) {
    const int base = lane * 16;
    int c = 0;
    #pragma unroll
    for (int t = 0; t < 16; ++t) {
        const int wi = base + t;
        if (wi < NWORDS) c += __popc(__ldg(w + wi));
    }
    int inc = c;
    #pragma unroll
    for (int off = 1; off < 32; off <<= 1) {
        int up = __shfl_up_sync(0xFFFFFFFFu, inc, off);
        if (lane >= off) inc += up;
    }
    const int tot = __shfl_sync(0xFFFFFFFFu, inc, 31);
    int r = inc - c;
    if (c > 0 && r < cap) {
        for (int t = 0; t < 16; ++t) {
            const int wi = base + t;
            unsigned x = (wi < NWORDS) ? __ldg(w + wi) : 0u;
            if (!x) continue;
            #pragma unroll
            for (int b = 0; b < 4; ++b)
                if ((x >> (8 * b)) & 1u) {
                    if (r < cap) s_out[r] = wi * 4 + b;
                    r++;
                }
        }
    }
    return tot;
}

// ---------------- IoU / flags + tail-block select/emit ----------------
// One warp per proposal (8/block, grid (250,4)). Last block (fence+atomic)
// runs select + emit for all 4 images and precomputes slim mask metadata.
__global__ void __launch_bounds__(256)
k_iou(const float* __restrict__ props,
      const int*   __restrict__ ids,
      const float* __restrict__ gtb,
      const uint4* __restrict__ masks_raw,
      float* __restrict__ out) {
    const int img  = blockIdx.y;
    const int wid  = threadIdx.x >> 5;
    const int lane = threadIdx.x & 31;
    const int prop = blockIdx.x * 8 + wid;   // 250*8 = 2000

    __shared__ float4 sgt[MAXGT];
    __shared__ int    sfl[MAXGT];   // bit0: gt_valid, bit1: crowd
    if (threadIdx.x < MAXGT) {
        const float* g = gtb + (img * MAXGT + threadIdx.x) * 4;
        float4 b; b.x = g[0]; b.y = g[1]; b.z = g[2]; b.w = g[3];
        sgt[threadIdx.x] = b;
        int id = ids[img * MAXGT + threadIdx.x];
        bool bv = (b.x != 0.f) || (b.y != 0.f) || (b.z != 0.f) || (b.w != 0.f);
        sfl[threadIdx.x] = ((bv && id > 0) ? 1 : 0) | ((bv && id < 0) ? 2 : 0);
    }
    __syncthreads();

    const float4 p = *(const float4*)(props + (img * NPROP + prop) * 4);
    const float py1 = p.x, px1 = p.y, py2 = p.z, px2 = p.w;
    const bool prop_valid = (py1 != 0.f) || (px1 != 0.f) || (py2 != 0.f) || (px2 != 0.f);
    const float a1 = __fmul_rn(__fsub_rn(py2, py1), __fsub_rn(px2, px1));

    float best = -INFINITY; int bi = 0;
    float crowd_max = -1.0f;
    #pragma unroll
    for (int t = 0; t < 2; ++t) {
        const int j = lane + 32 * t;
        float4 g = sgt[j];
        int fl = sfl[j];
        float ih = fmaxf(__fsub_rn(fminf(py2, g.z), fmaxf(py1, g.x)), 0.0f);
        float iw = fmaxf(__fsub_rn(fminf(px2, g.w), fmaxf(px1, g.y)), 0.0f);
        float inter = __fmul_rn(ih, iw);
        float a2 = __fmul_rn(__fsub_rn(g.z, g.x), __fsub_rn(g.w, g.y));
        float denom = __fadd_rn(__fsub_rn(__fadd_rn(a1, a2), inter), EPSF);
        float iou = __fdiv_rn(inter, denom);
        float ov = (fl & 1) ? iou : -1.0f;
        if (ov > best) { best = ov; bi = j; }   // j < j+32: first-max kept
        float cv = (fl & 2) ? iou : -1.0f;
        crowd_max = fmaxf(crowd_max, cv);
    }

    #pragma unroll
    for (int off = 16; off > 0; off >>= 1) {
        float ob = __shfl_xor_sync(0xFFFFFFFFu, best, off);
        int   oi = __shfl_xor_sync(0xFFFFFFFFu, bi, off);
        float oc = __shfl_xor_sync(0xFFFFFFFFu, crowd_max, off);
        if (ob > best || (ob == best && oi < bi)) { best = ob; bi = oi; }
        crowd_max = fmaxf(crowd_max, oc);
    }

    if (lane == 0) {
        bool pos = (best >= 0.5f) && prop_valid;
        bool neg = (best < 0.5f) && (crowd_max < 0.001f) && prop_valid && !pos;
        g_best[img][prop] = bi;
        g_posf[img][prop] = pos ? 1 : 0;
        g_negf[img][prop] = neg ? 1 : 0;
    }

    // ---- one-time mask dtype probe (block (0,0), warp 0) ----
    if (blockIdx.x == 0 && img == 0 && wid == 0) {
        int a = 0, b = 0, c = 0;
        #pragma unroll
        for (int t = 0; t < 8; ++t) {           // 8*32 uint4 = 4096 bytes
            uint4 v = __ldg(masks_raw + t * 32 + lane);
            unsigned ws[4] = {v.x, v.y, v.z, v.w};
            #pragma unroll
            for (int q = 0; q < 4; ++q) {
                unsigned w = ws[q];
                unsigned b0 = w & 0xFFu, b1 = (w >> 8) & 0xFFu;
                unsigned b2 = (w >> 16) & 0xFFu, b3 = (w >> 24) & 0xFFu;
                if (b0 > 1u || b1 > 1u || b2 > 1u || b3 > 1u) a = 1;
                if (b1 != 0u) b = 1;
                if (b1 == 1u || b2 == 1u || b3 == 1u) c = 1;
            }
        }
        unsigned am = __ballot_sync(0xFFFFFFFFu, a);
        unsigned bm = __ballot_sync(0xFFFFFFFFu, b);
        unsigned cm = __ballot_sync(0xFFFFFFFFu, c);
        if (lane == 0) {
            int fmt;
            if (am) fmt = bm ? 3 : 2;
            else    fmt = cm ? 0 : 1;
            g_mask_fmt = fmt;
        }
    }

    // ---- fence + atomic tail: last block runs select + emit ----
    __shared__ int s_last;
    __syncthreads();
    if (threadIdx.x == 0) {
        __threadfence();                          // publish flags/best
        int old = atomicAdd(&g_done, 1);
        s_last = (old == NIOU_BLOCKS - 1) ? 1 : 0;
        if (s_last) g_done = 0;                   // self-reset for next replay
    }
    __syncthreads();
    if (!s_last) return;
    __threadfence();                              // acquire all blocks' flags

    __shared__ int s_pos_idx[NIMG][PPOS];
    __shared__ int s_neg_idx[NIMG][NNEG];
    __shared__ int s_ptot[NIMG], s_ntot[NIMG];

    // 8 warps: warp w scans image w/2, pos if w even else neg.
    {
        const int im = wid >> 1;
        if (im < NIMG) {
            if ((wid & 1) == 0) {
                int pt = chunk_scan((const unsigned*)&g_posf[im][0], lane,
                                    PPOS, s_pos_idx[im]);
                if (lane == 0) s_ptot[im] = pt;
            } else {
                int nt = chunk_scan((const unsigned*)&g_negf[im][0], lane,
                                    NNEG, s_neg_idx[im]);
                if (lane == 0) s_ntot[im] = nt;
            }
        }
    }
    __syncthreads();

    for (int im = 0; im < NIMG; ++im) {
        const int pos_count = s_ptot[im] < PPOS ? s_ptot[im] : PPOS;
        const int k = threadIdx.x;
        if (k < NROIS) {
            float r0 = 0.f, r1 = 0.f, r2 = 0.f, r3 = 0.f;
            float cls = 0.f;
            float d0 = 0.f, d1 = 0.f, d2 = 0.f, d3 = 0.f;
            int   mg = -1;                       // mask metadata gt index
            if (k < PPOS) {
                if (k < pos_count) {
                    int idx = s_pos_idx[im][k];
                    const float* pp = props + (im * NPROP + idx) * 4;
                    r0 = pp[0]; r1 = pp[1]; r2 = pp[2]; r3 = pp[3];
                    int bg = g_best[im][idx];
                    mg = bg;
                    cls = (float)ids[im * MAXGT + bg];
                    const float* g = gtb + (im * MAXGT + bg) * 4;
                    float gy1 = g[0], gx1 = g[1], gy2 = g[2], gx2 = g[3];
                    float h  = fmaxf(__fsub_rn(r2, r0), EPSF);
                    float w  = fmaxf(__fsub_rn(r3, r1), EPSF);
                    float cy = __fadd_rn(r0, __fmul_rn(0.5f, h));
                    float cx = __fadd_rn(r1, __fmul_rn(0.5f, w));
                    float gh = fmaxf(__fsub_rn(gy2, gy1), EPSF);
                    float gw = fmaxf(__fsub_rn(gx2, gx1), EPSF);
                    float gcy = __fadd_rn(gy1, __fmul_rn(0.5f, gh));
                    float gcx = __fadd_rn(gx1, __fmul_rn(0.5f, gw));
                    d0 = __fmul_rn(__fdiv_rn(__fsub_rn(gcy, cy), h), RCP_01);
                    d1 = __fmul_rn(__fdiv_rn(__fsub_rn(gcx, cx), w), RCP_01);
                    d2 = __fmul_rn(logf(__fdiv_rn(gh, h)), RCP_02);
                    d3 = __fmul_rn(logf(__fdiv_rn(gw, w)), RCP_02);
                }
                // slim metadata for the mask kernel
                g_mgt[im][k]  = mg;
                g_mbox[im][k] = make_float4(r0, r1, r2, r3);
            } else {
                int neg_target = (int)(__fmul_rn((float)pos_count, RCP_033)) - pos_count;
                int avail = s_ntot[im] < NNEG ? s_ntot[im] : NNEG;
                int neg_count = neg_target < 0 ? 0 : (neg_target < avail ? neg_target : avail);
                int j = k - PPOS;
                if (j < neg_count) {
                    int idx = s_neg_idx[im][j];
                    const float* pp = props + (im * NPROP + idx) * 4;
                    r0 = pp[0]; r1 = pp[1]; r2 = pp[2]; r3 = pp[3];
                }
            }
            int row = im * NROIS + k;
            float* rois = out + OFF_ROIS + row * 4;
            rois[0] = r0; rois[1] = r1; rois[2] = r2; rois[3] = r3;
            out[OFF_CLS + row] = cls;
            float* del = out + OFF_DEL + row * 4;
            del[0] = d0; del[1] = d1; del[2] = d2; del[3] = d3;
        }
    }
}

// ---------- mask crop-resize: 2 pixels (1 float2) per thread ----------
// 313600 threads / 1225 blocks -> ~64 warps/SM resident, 8 independent
// gathers per thread: maximizes (warps/SM x MLP) feeding the DRAM queue.
// Slim metadata: 1 int + 1 float4 L1-broadcast load per thread.
__global__ void __launch_bounds__(256)
k_masks(const void* __restrict__ masks,
        float* __restrict__ out) {
    const int q = blockIdx.x * 256 + threadIdx.x;
    if (q >= NQ2) return;
    const int img = q / (NROIS * 392);
    const int rem = q % (NROIS * 392);
    const int k   = rem / 392;
    const int t2  = (rem % 392) * 2;

    float v0 = 0.0f, v1 = 0.0f;
    if (k < PPOS) {
        const int g = __ldg(&g_mgt[img][k]);
        if (g >= 0) {
            const int fmt = g_mask_fmt;
            const float4 pb = __ldg(&g_mbox[img][k]);
            const float y1 = pb.x, x1 = pb.y, y2 = pb.z, x2 = pb.w;
            float vv[2];
            #pragma unroll
            for (int u = 0; u < 2; ++u) {
                const int t = t2 + u;
                const int i = t / MW, j = t % MW;
                float iy = __fmul_rn((float)i, RCP_27);
                float ix = __fmul_rn((float)j, RCP_27);
                float ys = __fmul_rn(__fadd_rn(y1, __fmul_rn(iy, __fsub_rn(y2, y1))), (float)(HH - 1));
                float xs = __fmul_rn(__fadd_rn(x1, __fmul_rn(ix, __fsub_rn(x2, x1))), (float)(WW - 1));
                float y0f = floorf(ys), x0f = floorf(xs);
                float ly = __fsub_rn(ys, y0f);
                float lx = __fsub_rn(xs, x0f);
                int y0  = min(max((int)y0f, 0), HH - 1);
                int y1i = min(y0 + 1, HH - 1);
                int x0  = min(max((int)x0f, 0), WW - 1);
                int x1i = min(x0 + 1, WW - 1);
                int rowbase0 = (img * HH + y0)  * WW;
                int rowbase1 = (img * HH + y1i) * WW;
                float v00 = mask_at(masks, fmt, (rowbase0 + x0)  * MAXGT + g);
                float v01 = mask_at(masks, fmt, (rowbase0 + x1i) * MAXGT + g);
                float v10 = mask_at(masks, fmt, (rowbase1 + x0)  * MAXGT + g);
                float v11 = mask_at(masks, fmt, (rowbase1 + x1i) * MAXGT + g);
                float omlx = __fsub_rn(1.0f, lx);
                float omly = __fsub_rn(1.0f, ly);
                float top = __fadd_rn(__fmul_rn(v00, omlx), __fmul_rn(v01, lx));
                float bot = __fadd_rn(__fmul_rn(v10, omlx), __fmul_rn(v11, lx));
                vv[u] = rintf(__fadd_rn(__fmul_rn(top, omly), __fmul_rn(bot, ly)));  // half-to-even
            }
            v0 = vv[0]; v1 = vv[1];
        }
    }
    *(float2*)(out + OFF_MSK + (img * NROIS + k) * (MH * MW) + t2) = make_float2(v0, v1);
}

// ---------------- launch ----------------
extern "C" void kernel_launch(void* const* d_in, const int* in_sizes, int n_in,
                              void* d_out, int out_size) {
    const float* props = (const float*)d_in[0];
    const int*   ids   = (const int*)  d_in[1];
    const float* gtb   = (const float*)d_in[2];
    const void*  masks = d_in[3];
    float* out = (float*)d_out;

    k_iou<<<dim3(NPROP / 8, NIMG), 256>>>(props, ids, gtb, (const uint4*)masks, out);
    k_masks<<<(NQ2 + 255) / 256, 256>>>(masks, out);
}

// round 15
// speedup vs baseline: 1.1678x; 1.0039x over previous
#include <cuda_runtime.h>
#include <cuda_bf16.h>
#include <math.h>

#define NIMG   4
#define NPROP  2000
#define MAXGT  64
#define HH     512
#define WW     512
#define PPOS   66
#define NNEG   134
#define NROIS  200
#define MH     28
#define MW     28
#define EPSF   1e-8f
#define NWORDS (NPROP / 4)        // 500 packed flag words per image
#define NIOU_BLOCKS (NPROP / 8 * NIMG)          // 1000 blocks in k_iou grid
#define NQP    (NIMG * PPOS * (MH * MW))        // 206976 gather pixels (k<PPOS only)
#define NZ4    (NIMG * NNEG * (MH * MW) / 4)    // 105056 float4 zero units (k>=PPOS)

// Output layout (float32, concatenated flattened tuple):
//   rois    [4][200][4]     @ 0      (3200)
//   class   [4][200]        @ 3200   (800)
//   deltas  [4][200][4]     @ 4000   (3200)
//   masks   [4][200][28][28]@ 7200   (627200)
#define OFF_ROIS  0
#define OFF_CLS   3200
#define OFF_DEL   4000
#define OFF_MSK   7200

// XLA rewrites x / const into x * (1/const) (algebraic simplifier).
#define RCP_033  (1.0f / 0.33f)   // 66*r rounds to exactly 200.0f
#define RCP_01   (1.0f / 0.1f)    // exactly 10.0f
#define RCP_02   (1.0f / 0.2f)    // exactly 5.0f
#define RCP_27   (1.0f / 27.0f)

// ---------------- device scratch (no allocations allowed) ----------------
__device__ int            g_best[NIMG][NPROP];
__device__ unsigned char  g_posf[NIMG][NPROP];   // 0/1 bytes
__device__ unsigned char  g_negf[NIMG][NPROP];
__device__ int            g_mgt[NIMG][PPOS];     // gt index per pos row, -1 = zero row
__device__ float4         g_mbox[NIMG][PPOS];    // roi box per pos row
__device__ int            g_mask_fmt;            // 0=u8, 1=i32, 2=f32, 3=bf16
__device__ int            g_done = 0;            // fence+atomic tail counter

__device__ __forceinline__ float mask_at(const void* m, int fmt, int idx) {
    switch (fmt) {
        case 0:  return (float)__ldg((const unsigned char*)m + idx);
        case 1:  return (float)__ldg((const int*)m + idx);
        case 3: {
            unsigned short u = __ldg((const unsigned short*)m + idx);
            __nv_bfloat16 v;
            *(unsigned short*)&v = u;
            return __bfloat162float(v);
        }
        default: return __ldg((const float*)m + idx);
    }
}

// ---- stable first-k chunk compaction (warp-collective) ----
__device__ __forceinline__ int chunk_scan(const unsigned* __restrict__ w,
                                          int lane, int cap, int* s_out) {
    const int base = lane * 16;
    int c = 0;
    #pragma unroll
    for (int t = 0; t < 16; ++t) {
        const int wi = base + t;
        if (wi < NWORDS) c += __popc(__ldg(w + wi));
    }
    int inc = c;
    #pragma unroll
    for (int off = 1; off < 32; off <<= 1) {
        int up = __shfl_up_sync(0xFFFFFFFFu, inc, off);
        if (lane >= off) inc += up;
    }
    const int tot = __shfl_sync(0xFFFFFFFFu, inc, 31);
    int r = inc - c;
    if (c > 0 && r < cap) {
        for (int t = 0; t < 16; ++t) {
            const int wi = base + t;
            unsigned x = (wi < NWORDS) ? __ldg(w + wi) : 0u;
            if (!x) continue;
            #pragma unroll
            for (int b = 0; b < 4; ++b)
                if ((x >> (8 * b)) & 1u) {
                    if (r < cap) s_out[r] = wi * 4 + b;
                    r++;
                }
        }
    }
    return tot;
}

// ---------------- IoU / flags + static mask zero-fill + tail select/emit ----
// One warp per proposal (8/block, grid (250,4)). Every block also zero-fills
// its slice of the unconditionally-zero mask rows (k>=PPOS) — no dependency.
// Last block (fence+atomic) runs select + emit and writes slim mask metadata.
__global__ void __launch_bounds__(256)
k_iou(const float* __restrict__ props,
      const int*   __restrict__ ids,
      const float* __restrict__ gtb,
      const uint4* __restrict__ masks_raw,
      float* __restrict__ out) {
    const int img  = blockIdx.y;
    const int wid  = threadIdx.x >> 5;
    const int lane = threadIdx.x & 31;
    const int prop = blockIdx.x * 8 + wid;   // 250*8 = 2000

    // ---- static zero-fill of mask rows [PPOS, NROIS) (no dependency) ----
    {
        const int gtid  = (img * (NPROP / 8) + blockIdx.x) * 256 + threadIdx.x;
        const int nthr  = NIOU_BLOCKS * 256;             // 256000
        for (int z = gtid; z < NZ4; z += nthr) {         // <=1 iter for most
            const int im  = z / (NNEG * 196);
            const int zr  = z % (NNEG * 196);
            const int kk  = PPOS + zr / 196;
            const int off = (zr % 196) * 4;
            *(float4*)(out + OFF_MSK + (im * NROIS + kk) * (MH * MW) + off) =
                make_float4(0.f, 0.f, 0.f, 0.f);
        }
    }

    __shared__ float4 sgt[MAXGT];
    __shared__ int    sfl[MAXGT];   // bit0: gt_valid, bit1: crowd
    if (threadIdx.x < MAXGT) {
        const float* g = gtb + (img * MAXGT + threadIdx.x) * 4;
        float4 b; b.x = g[0]; b.y = g[1]; b.z = g[2]; b.w = g[3];
        sgt[threadIdx.x] = b;
        int id = ids[img * MAXGT + threadIdx.x];
        bool bv = (b.x != 0.f) || (b.y != 0.f) || (b.z != 0.f) || (b.w != 0.f);
        sfl[threadIdx.x] = ((bv && id > 0) ? 1 : 0) | ((bv && id < 0) ? 2 : 0);
    }
    __syncthreads();

    const float4 p = *(const float4*)(props + (img * NPROP + prop) * 4);
    const float py1 = p.x, px1 = p.y, py2 = p.z, px2 = p.w;
    const bool prop_valid = (py1 != 0.f) || (px1 != 0.f) || (py2 != 0.f) || (px2 != 0.f);
    const float a1 = __fmul_rn(__fsub_rn(py2, py1), __fsub_rn(px2, px1));

    float best = -INFINITY; int bi = 0;
    float crowd_max = -1.0f;
    #pragma unroll
    for (int t = 0; t < 2; ++t) {
        const int j = lane + 32 * t;
        float4 g = sgt[j];
        int fl = sfl[j];
        float ih = fmaxf(__fsub_rn(fminf(py2, g.z), fmaxf(py1, g.x)), 0.0f);
        float iw = fmaxf(__fsub_rn(fminf(px2, g.w), fmaxf(px1, g.y)), 0.0f);
        float inter = __fmul_rn(ih, iw);
        float a2 = __fmul_rn(__fsub_rn(g.z, g.x), __fsub_rn(g.w, g.y));
        float denom = __fadd_rn(__fsub_rn(__fadd_rn(a1, a2), inter), EPSF);
        float iou = __fdiv_rn(inter, denom);
        float ov = (fl & 1) ? iou : -1.0f;
        if (ov > best) { best = ov; bi = j; }   // j < j+32: first-max kept
        float cv = (fl & 2) ? iou : -1.0f;
        crowd_max = fmaxf(crowd_max, cv);
    }

    #pragma unroll
    for (int off = 16; off > 0; off >>= 1) {
        float ob = __shfl_xor_sync(0xFFFFFFFFu, best, off);
        int   oi = __shfl_xor_sync(0xFFFFFFFFu, bi, off);
        float oc = __shfl_xor_sync(0xFFFFFFFFu, crowd_max, off);
        if (ob > best || (ob == best && oi < bi)) { best = ob; bi = oi; }
        crowd_max = fmaxf(crowd_max, oc);
    }

    if (lane == 0) {
        bool pos = (best >= 0.5f) && prop_valid;
        bool neg = (best < 0.5f) && (crowd_max < 0.001f) && prop_valid && !pos;
        g_best[img][prop] = bi;
        g_posf[img][prop] = pos ? 1 : 0;
        g_negf[img][prop] = neg ? 1 : 0;
    }

    // ---- one-time mask dtype probe (block (0,0), warp 0) ----
    if (blockIdx.x == 0 && img == 0 && wid == 0) {
        int a = 0, b = 0, c = 0;
        #pragma unroll
        for (int t = 0; t < 8; ++t) {           // 8*32 uint4 = 4096 bytes
            uint4 v = __ldg(masks_raw + t * 32 + lane);
            unsigned ws[4] = {v.x, v.y, v.z, v.w};
            #pragma unroll
            for (int q = 0; q < 4; ++q) {
                unsigned w = ws[q];
                unsigned b0 = w & 0xFFu, b1 = (w >> 8) & 0xFFu;
                unsigned b2 = (w >> 16) & 0xFFu, b3 = (w >> 24) & 0xFFu;
                if (b0 > 1u || b1 > 1u || b2 > 1u || b3 > 1u) a = 1;
                if (b1 != 0u) b = 1;
                if (b1 == 1u || b2 == 1u || b3 == 1u) c = 1;
            }
        }
        unsigned am = __ballot_sync(0xFFFFFFFFu, a);
        unsigned bm = __ballot_sync(0xFFFFFFFFu, b);
        unsigned cm = __ballot_sync(0xFFFFFFFFu, c);
        if (lane == 0) {
            int fmt;
            if (am) fmt = bm ? 3 : 2;
            else    fmt = cm ? 0 : 1;
            g_mask_fmt = fmt;
        }
    }

    // ---- fence + atomic tail: last block runs select + emit ----
    __shared__ int s_last;
    __syncthreads();
    if (threadIdx.x == 0) {
        __threadfence();                          // publish flags/best
        int old = atomicAdd(&g_done, 1);
        s_last = (old == NIOU_BLOCKS - 1) ? 1 : 0;
        if (s_last) g_done = 0;                   // self-reset for next replay
    }
    __syncthreads();
    if (!s_last) return;
    __threadfence();                              // acquire all blocks' flags

    __shared__ int s_pos_idx[NIMG][PPOS];
    __shared__ int s_neg_idx[NIMG][NNEG];
    __shared__ int s_ptot[NIMG], s_ntot[NIMG];

    // 8 warps: warp w scans image w/2, pos if w even else neg.
    {
        const int im = wid >> 1;
        if (im < NIMG) {
            if ((wid & 1) == 0) {
                int pt = chunk_scan((const unsigned*)&g_posf[im][0], lane,
                                    PPOS, s_pos_idx[im]);
                if (lane == 0) s_ptot[im] = pt;
            } else {
                int nt = chunk_scan((const unsigned*)&g_negf[im][0], lane,
                                    NNEG, s_neg_idx[im]);
                if (lane == 0) s_ntot[im] = nt;
            }
        }
    }
    __syncthreads();

    for (int im = 0; im < NIMG; ++im) {
        const int pos_count = s_ptot[im] < PPOS ? s_ptot[im] : PPOS;
        const int k = threadIdx.x;
        if (k < NROIS) {
            float r0 = 0.f, r1 = 0.f, r2 = 0.f, r3 = 0.f;
            float cls = 0.f;
            float d0 = 0.f, d1 = 0.f, d2 = 0.f, d3 = 0.f;
            int   mg = -1;                       // mask metadata gt index
            if (k < PPOS) {
                if (k < pos_count) {
                    int idx = s_pos_idx[im][k];
                    const float* pp = props + (im * NPROP + idx) * 4;
                    r0 = pp[0]; r1 = pp[1]; r2 = pp[2]; r3 = pp[3];
                    int bg = g_best[im][idx];
                    mg = bg;
                    cls = (float)ids[im * MAXGT + bg];
                    const float* g = gtb + (im * MAXGT + bg) * 4;
                    float gy1 = g[0], gx1 = g[1], gy2 = g[2], gx2 = g[3];
                    float h  = fmaxf(__fsub_rn(r2, r0), EPSF);
                    float w  = fmaxf(__fsub_rn(r3, r1), EPSF);
                    float cy = __fadd_rn(r0, __fmul_rn(0.5f, h));
                    float cx = __fadd_rn(r1, __fmul_rn(0.5f, w));
                    float gh = fmaxf(__fsub_rn(gy2, gy1), EPSF);
                    float gw = fmaxf(__fsub_rn(gx2, gx1), EPSF);
                    float gcy = __fadd_rn(gy1, __fmul_rn(0.5f, gh));
                    float gcx = __fadd_rn(gx1, __fmul_rn(0.5f, gw));
                    d0 = __fmul_rn(__fdiv_rn(__fsub_rn(gcy, cy), h), RCP_01);
                    d1 = __fmul_rn(__fdiv_rn(__fsub_rn(gcx, cx), w), RCP_01);
                    d2 = __fmul_rn(logf(__fdiv_rn(gh, h)), RCP_02);
                    d3 = __fmul_rn(logf(__fdiv_rn(gw, w)), RCP_02);
                }
                // slim metadata for the mask kernel
                g_mgt[im][k]  = mg;
                g_mbox[im][k] = make_float4(r0, r1, r2, r3);
            } else {
                int neg_target = (int)(__fmul_rn((float)pos_count, RCP_033)) - pos_count;
                int avail = s_ntot[im] < NNEG ? s_ntot[im] : NNEG;
                int neg_count = neg_target < 0 ? 0 : (neg_target < avail ? neg_target : avail);
                int j = k - PPOS;
                if (j < neg_count) {
                    int idx = s_neg_idx[im][j];
                    const float* pp = props + (im * NPROP + idx) * 4;
                    r0 = pp[0]; r1 = pp[1]; r2 = pp[2]; r3 = pp[3];
                }
            }
            int row = im * NROIS + k;
            float* rois = out + OFF_ROIS + row * 4;
            rois[0] = r0; rois[1] = r1; rois[2] = r2; rois[3] = r3;
            out[OFF_CLS + row] = cls;
            float* del = out + OFF_DEL + row * 4;
            del[0] = d0; del[1] = d1; del[2] = d2; del[3] = d3;
        }
    }
}

// ---------- mask crop-resize: 1 pixel per thread, pos rows ONLY ----------
// Grid covers k<PPOS only (206976 threads, 809 blocks): every resident warp
// streams real gathers for the whole kernel (4 LDG/thread = 128/warp, well
// past the ~55/warp outstanding cap). Rows >= pos_count write zeros (g<0).
__global__ void __launch_bounds__(256)
k_masks(const void* __restrict__ masks,
        float* __restrict__ out) {
    const int q = blockIdx.x * 256 + threadIdx.x;
    if (q >= NQP) return;
    const int img = q / (PPOS * 784);
    const int rem = q % (PPOS * 784);
    const int k   = rem / 784;
    const int t   = rem % 784;

    float val = 0.0f;
    const int g = __ldg(&g_mgt[img][k]);
    if (g >= 0) {
        const int fmt = g_mask_fmt;
        const float4 pb = __ldg(&g_mbox[img][k]);
        const float y1 = pb.x, x1 = pb.y, y2 = pb.z, x2 = pb.w;
        const int i = t / MW, j = t % MW;
        float iy = __fmul_rn((float)i, RCP_27);
        float ix = __fmul_rn((float)j, RCP_27);
        float ys = __fmul_rn(__fadd_rn(y1, __fmul_rn(iy, __fsub_rn(y2, y1))), (float)(HH - 1));
        float xs = __fmul_rn(__fadd_rn(x1, __fmul_rn(ix, __fsub_rn(x2, x1))), (float)(WW - 1));
        float y0f = floorf(ys), x0f = floorf(xs);
        float ly = __fsub_rn(ys, y0f);
        float lx = __fsub_rn(xs, x0f);
        int y0  = min(max((int)y0f, 0), HH - 1);
        int y1i = min(y0 + 1, HH - 1);
        int x0  = min(max((int)x0f, 0), WW - 1);
        int x1i = min(x0 + 1, WW - 1);
        int rowbase0 = (img * HH + y0)  * WW;
        int rowbase1 = (img * HH + y1i) * WW;
        float v00 = mask_at(masks, fmt, (rowbase0 + x0)  * MAXGT + g);
        float v01 = mask_at(masks, fmt, (rowbase0 + x1i) * MAXGT + g);
        float v10 = mask_at(masks, fmt, (rowbase1 + x0)  * MAXGT + g);
        float v11 = mask_at(masks, fmt, (rowbase1 + x1i) * MAXGT + g);
        float omlx = __fsub_rn(1.0f, lx);
        float omly = __fsub_rn(1.0f, ly);
        float top = __fadd_rn(__fmul_rn(v00, omlx), __fmul_rn(v01, lx));
        float bot = __fadd_rn(__fmul_rn(v10, omlx), __fmul_rn(v11, lx));
        val = rintf(__fadd_rn(__fmul_rn(top, omly), __fmul_rn(bot, ly)));  // half-to-even
    }
    out[OFF_MSK + (img * NROIS + k) * (MH * MW) + t] = val;
}

// ---------------- launch ----------------
extern "C" void kernel_launch(void* const* d_in, const int* in_sizes, int n_in,
                              void* d_out, int out_size) {
    const float* props = (const float*)d_in[0];
    const int*   ids   = (const int*)  d_in[1];
    const float* gtb   = (const float*)d_in[2];
    const void*  masks = d_in[3];
    float* out = (float*)d_out;

    k_iou<<<dim3(NPROP / 8, NIMG), 256>>>(props, ids, gtb, (const uint4*)masks, out);
    k_masks<<<(NQP + 255) / 256, 256>>>(masks, out);
}